// round 5
// baseline (speedup 1.0000x reference)
#include <cuda_runtime.h>
#include <cuda_bf16.h>
#include <math.h>

#define B_ 64
#define T_ 1024
#define D_ 512
#define U_ 1024
#define BT (B_ * T_)

// ---------------- device scratch (no allocation allowed) ----------------
__device__ __align__(128) __nv_bfloat16 g_fhi[BT * D_];     // 64 MB
__device__ __align__(128) __nv_bfloat16 g_flo[BT * D_];     // 64 MB
__device__ __align__(128) __nv_bfloat16 g_w1t_hi[U_ * D_];  // [n][k], 1 MB
__device__ __align__(128) __nv_bfloat16 g_w1t_lo[U_ * D_];
__device__ float g_projh[B_ * U_];
__device__ float g_lpart[4][BT];   // per-n-quarter logit partials

// ---------------- PTX helpers ----------------
__device__ __forceinline__ unsigned smem_u32(const void* p) {
    unsigned a;
    asm("{ .reg .u64 t; cvta.to.shared.u64 t, %1; cvt.u32.u64 %0, t; }"
        : "=r"(a) : "l"(p));
    return a;
}
__device__ __forceinline__ void cpa16(unsigned dst, const void* src) {
    asm volatile("cp.async.cg.shared.global [%0], [%1], 16;" :: "r"(dst), "l"(src));
}
__device__ __forceinline__ void cpa_commit() { asm volatile("cp.async.commit_group;"); }
__device__ __forceinline__ void ldsm4(unsigned addr, unsigned& r0, unsigned& r1,
                                      unsigned& r2, unsigned& r3) {
    asm volatile("ldmatrix.sync.aligned.m8n8.x4.shared.b16 {%0,%1,%2,%3}, [%4];"
                 : "=r"(r0), "=r"(r1), "=r"(r2), "=r"(r3) : "r"(addr));
}
__device__ __forceinline__ void mma16816(float* c, unsigned a0, unsigned a1,
                                         unsigned a2, unsigned a3,
                                         unsigned b0, unsigned b1) {
    asm volatile(
        "mma.sync.aligned.m16n8k16.row.col.f32.bf16.bf16.f32 "
        "{%0,%1,%2,%3}, {%4,%5,%6,%7}, {%8,%9}, {%0,%1,%2,%3};"
        : "+f"(c[0]), "+f"(c[1]), "+f"(c[2]), "+f"(c[3])
        : "r"(a0), "r"(a1), "r"(a2), "r"(a3), "r"(b0), "r"(b1));
}

// ---------------- smem layout for score kernel ----------------
#define STAGE 49152            // A (128x64 bf16 = 16KB) + B (256x64 bf16 = 32KB)
#define OFF_BT 16384           // B offset within stage
#define OFF_PH 196608          // 256 floats
#define OFF_V  197632          // 256 floats
#define OFF_RED 198656         // 128 x 8 floats
#define SMEM_TOTAL 202752

// ---------------------------------------------------------------------------
// split feat fp32 -> bf16 hi/lo
// ---------------------------------------------------------------------------
__global__ void fsplit_kernel(const float* __restrict__ feat) {
    long i = (long)blockIdx.x * 256 + threadIdx.x;   // one float4 per thread
    float4 v = ((const float4*)feat)[i];
    __nv_bfloat16 ha = __float2bfloat16(v.x), hb = __float2bfloat16(v.y);
    __nv_bfloat16 hc = __float2bfloat16(v.z), hd = __float2bfloat16(v.w);
    float la = v.x - __bfloat162float(ha), lb = v.y - __bfloat162float(hb);
    float lc = v.z - __bfloat162float(hc), ld = v.w - __bfloat162float(hd);
    uint2 hw, lw;
    hw.x = (unsigned)__bfloat16_as_ushort(ha) | ((unsigned)__bfloat16_as_ushort(hb) << 16);
    hw.y = (unsigned)__bfloat16_as_ushort(hc) | ((unsigned)__bfloat16_as_ushort(hd) << 16);
    lw.x = (unsigned)__bfloat16_as_ushort(__float2bfloat16(la)) |
           ((unsigned)__bfloat16_as_ushort(__float2bfloat16(lb)) << 16);
    lw.y = (unsigned)__bfloat16_as_ushort(__float2bfloat16(lc)) |
           ((unsigned)__bfloat16_as_ushort(__float2bfloat16(ld)) << 16);
    ((uint2*)g_fhi)[i] = hw;
    ((uint2*)g_flo)[i] = lw;
}

// ---------------------------------------------------------------------------
// transpose + split W1 [D,U] -> g_w1t_{hi,lo} [U][D]
// ---------------------------------------------------------------------------
__global__ void w1split_kernel(const float* __restrict__ W1) {
    __shared__ float tile[32][33];
    const int n0 = blockIdx.x * 32, k0 = blockIdx.y * 32;
    const int tx = threadIdx.x;
    for (int r = threadIdx.y; r < 32; r += 8)
        tile[r][tx] = W1[(size_t)(k0 + r) * U_ + n0 + tx];
    __syncthreads();
    for (int rr = threadIdx.y; rr < 32; rr += 8) {
        float v = tile[tx][rr];                   // W1[k0+tx][n0+rr]
        __nv_bfloat16 h = __float2bfloat16(v);
        size_t o = (size_t)(n0 + rr) * D_ + k0 + tx;
        g_w1t_hi[o] = h;
        g_w1t_lo[o] = __float2bfloat16(v - __bfloat162float(h));
    }
}

// ---------------------------------------------------------------------------
// proj_h[b,u] = hidden[b,:] @ W2[:,u] + W2_b[u];  grid (U/128, B/8), 128 thr
// ---------------------------------------------------------------------------
__global__ void projh_kernel(const float* __restrict__ hidden,
                             const float* __restrict__ W2,
                             const float* __restrict__ W2b) {
    __shared__ __align__(16) float hs[8][D_];
    const int tid = threadIdx.x;
    const int u = blockIdx.x * 128 + tid;
    const int b0 = blockIdx.y * 8;
#pragma unroll
    for (int i = 0; i < 8; i++)
        ((float4*)hs)[tid + i * 128] = ((const float4*)(hidden + (size_t)b0 * D_))[tid + i * 128];
    __syncthreads();
    float acc[8];
#pragma unroll
    for (int i = 0; i < 8; i++) acc[i] = 0.f;
#pragma unroll 4
    for (int k = 0; k < D_; k++) {
        float w = W2[(size_t)k * U_ + u];
#pragma unroll
        for (int bb = 0; bb < 8; bb++) acc[bb] += hs[bb][k] * w;
    }
    float bias = W2b[u];
#pragma unroll
    for (int bb = 0; bb < 8; bb++) g_projh[(size_t)(b0 + bb) * U_ + u] = acc[bb] + bias;
}

// ---------------------------------------------------------------------------
// score kernel: mma.sync bf16 (3-term split) GEMM + tanh + V-dot epilogue
// CTA tile 128(M) x 256(N), K chunks of 64, virtual K = 3*512 = 1536 (24 chunks)
// grid (4 n-quarters, BT/128), 512 threads (16 warps, 64x32 warp tiles)
// ---------------------------------------------------------------------------
__global__ void __launch_bounds__(512, 1)
score_kernel(const float* __restrict__ W1b, const float* __restrict__ Vw) {
    extern __shared__ __align__(1024) char smem[];
    const unsigned sbase = smem_u32(smem);
    const int tid = threadIdx.x;
    const int wid = tid >> 5, lid = tid & 31;
    const int wm = wid & 1, wn = wid >> 1;       // 2 x 8 warp grid, tile 64m x 32n
    const int nq = blockIdx.x;
    const int bt0 = blockIdx.y * 128;
    const int b = bt0 >> 10;
    const int n0 = nq * 256;
    float* shPh = (float*)(smem + OFF_PH);
    float* shV  = (float*)(smem + OFF_V);
    float (*red)[8] = (float(*)[8])(smem + OFF_RED);

    if (tid < 256) {
        shPh[tid] = g_projh[(size_t)b * U_ + n0 + tid] + W1b[n0 + tid];
        shV[tid]  = Vw[n0 + tid];
    }

    // ---- loop-invariant cp.async offsets (derived by constant strides) ----
    // A: 1024 granules of 16B, thread handles o = tid, tid+512 (row step 64)
    // B: 2048 granules, o = tid + i*512, i<4 (row step 64)
    unsigned a_src0, a_dst0, b_src0, b_dst0;
    {
        int row = tid >> 3, c16 = tid & 7;
        a_src0 = (unsigned)((bt0 + row) * D_ + c16 * 8);
        a_dst0 = row * 128 + ((c16 ^ (row & 7)) * 16);
        b_src0 = (unsigned)((n0 + row) * D_ + c16 * 8);
        b_dst0 = OFF_BT + row * 128 + ((c16 ^ (row & 7)) * 16);
    }

    // ---- loop-invariant ldmatrix bases (kk enters via XOR of kk*32) ----
    const int lrow = lid & 15;
    const int lch  = lid >> 4;
    unsigned abase0, bbase0;
    {
        int row = wm * 64 + lrow;
        abase0 = row * 128 + ((lch ^ (row & 7)) * 16);
        int rowb = wn * 32 + lrow;
        bbase0 = OFF_BT + rowb * 128 + ((lch ^ (rowb & 7)) * 16);
    }

    float Cr[4][4][4];
#pragma unroll
    for (int mt = 0; mt < 4; mt++)
#pragma unroll
        for (int nt = 0; nt < 4; nt++)
#pragma unroll
            for (int j = 0; j < 4; j++) Cr[mt][nt][j] = 0.f;

    // ---- prologue: fill 3 stages ----
#pragma unroll
    for (int c = 0; c < 3; c++) {
        const int k0 = c * 64;
        const __nv_bfloat16* Asrc = g_fhi + k0;   // chunks 0..2 are seg 0
        const __nv_bfloat16* Bsrc = g_w1t_hi + k0;
        const unsigned stg = sbase + c * STAGE;
#pragma unroll
        for (int i = 0; i < 2; i++)
            cpa16(stg + a_dst0 + i * 8192, Asrc + a_src0 + i * 32768);
#pragma unroll
        for (int i = 0; i < 4; i++)
            cpa16(stg + b_dst0 + i * 8192, Bsrc + b_src0 + i * 32768);
        cpa_commit();
    }

    for (int c = 0; c < 24; c++) {
        asm volatile("cp.async.wait_group 2;" ::: "memory");
        __syncthreads();
        if (c + 3 < 24) {
            const int cn = c + 3;
            const int seg = cn >> 3;
            const int k0 = (cn & 7) * 64;
            const __nv_bfloat16* Asrc = ((seg == 1) ? g_flo : g_fhi) + k0;
            const __nv_bfloat16* Bsrc = ((seg == 2) ? g_w1t_lo : g_w1t_hi) + k0;
            const unsigned stg = sbase + (cn & 3) * STAGE;
#pragma unroll
            for (int i = 0; i < 2; i++)
                cpa16(stg + a_dst0 + i * 8192, Asrc + a_src0 + i * 32768);
#pragma unroll
            for (int i = 0; i < 4; i++)
                cpa16(stg + b_dst0 + i * 8192, Bsrc + b_src0 + i * 32768);
        }
        cpa_commit();

        const unsigned Ab = sbase + (c & 3) * STAGE;
#pragma unroll
        for (int kk = 0; kk < 4; kk++) {     // four k16 steps in the k64 chunk
            const unsigned kx = kk << 5;
            unsigned a[4][4];
#pragma unroll
            for (int mt = 0; mt < 4; mt++)
                ldsm4(Ab + ((abase0 + mt * 2048) ^ kx),
                      a[mt][0], a[mt][1], a[mt][2], a[mt][3]);
            unsigned bf[4][2];
#pragma unroll
            for (int np = 0; np < 2; np++) { // each x4 (non-trans) = two n8 tiles
                unsigned t0, t1, t2, t3;
                ldsm4(Ab + ((bbase0 + np * 2048) ^ kx), t0, t1, t2, t3);
                bf[np * 2][0] = t0; bf[np * 2][1] = t2;
                bf[np * 2 + 1][0] = t1; bf[np * 2 + 1][1] = t3;
            }
#pragma unroll
            for (int mt = 0; mt < 4; mt++)
#pragma unroll
                for (int nt = 0; nt < 4; nt++)
                    mma16816(Cr[mt][nt], a[mt][0], a[mt][1], a[mt][2], a[mt][3],
                             bf[nt][0], bf[nt][1]);
        }
    }

    // ---- epilogue: tanh + V-dot on fragments ----
    float p0[4], p1[4];
#pragma unroll
    for (int mt = 0; mt < 4; mt++) { p0[mt] = 0.f; p1[mt] = 0.f; }
#pragma unroll
    for (int mt = 0; mt < 4; mt++)
#pragma unroll
        for (int nt = 0; nt < 4; nt++) {
            int nc = wn * 32 + nt * 8 + (lid & 3) * 2;
            float ph0 = shPh[nc], ph1 = shPh[nc + 1];
            float v0 = shV[nc], v1 = shV[nc + 1];
            p0[mt] += tanhf(Cr[mt][nt][0] + ph0) * v0
                    + tanhf(Cr[mt][nt][1] + ph1) * v1;
            p1[mt] += tanhf(Cr[mt][nt][2] + ph0) * v0
                    + tanhf(Cr[mt][nt][3] + ph1) * v1;
        }
#pragma unroll
    for (int mt = 0; mt < 4; mt++) {
        p0[mt] += __shfl_xor_sync(0xFFFFFFFFu, p0[mt], 1);
        p0[mt] += __shfl_xor_sync(0xFFFFFFFFu, p0[mt], 2);
        p1[mt] += __shfl_xor_sync(0xFFFFFFFFu, p1[mt], 1);
        p1[mt] += __shfl_xor_sync(0xFFFFFFFFu, p1[mt], 2);
    }
    if ((lid & 3) == 0) {
#pragma unroll
        for (int mt = 0; mt < 4; mt++) {
            int rl = wm * 64 + mt * 16 + (lid >> 2);
            red[rl][wn] = p0[mt];
            red[rl + 8][wn] = p1[mt];
        }
    }
    __syncthreads();
    if (tid < 128) {
        float s = red[tid][0] + red[tid][1] + red[tid][2] + red[tid][3]
                + red[tid][4] + red[tid][5] + red[tid][6] + red[tid][7];
        g_lpart[nq][bt0 + tid] = s;
    }
}

// ---------------------------------------------------------------------------
// softmax over T + attention weights + context vector
// ---------------------------------------------------------------------------
__global__ void softmax_ctx_kernel(const float* __restrict__ feat,
                                   const float* __restrict__ Vb,
                                   float* __restrict__ out) {
    __shared__ float ws[T_];
    __shared__ float rbuf[128];
    const int b = blockIdx.x;
    const int ds = blockIdx.y;
    const int tid = threadIdx.x;

    float l[8];
    float mx = -1e30f;
    const float vb = Vb[0];
#pragma unroll
    for (int i = 0; i < 8; i++) {
        int idx = b * T_ + tid * 8 + i;
        l[i] = g_lpart[0][idx] + g_lpart[1][idx] + g_lpart[2][idx] + g_lpart[3][idx] + vb;
        mx = fmaxf(mx, l[i]);
    }
    rbuf[tid] = mx;
    __syncthreads();
    for (int s = 64; s > 0; s >>= 1) {
        if (tid < s) rbuf[tid] = fmaxf(rbuf[tid], rbuf[tid + s]);
        __syncthreads();
    }
    mx = rbuf[0];
    __syncthreads();

    float ssum = 0.f;
#pragma unroll
    for (int i = 0; i < 8; i++) {
        l[i] = expf(l[i] - mx);
        ssum += l[i];
    }
    rbuf[tid] = ssum;
    __syncthreads();
    for (int s = 64; s > 0; s >>= 1) {
        if (tid < s) rbuf[tid] += rbuf[tid + s];
        __syncthreads();
    }
    const float inv = 1.0f / rbuf[0];
#pragma unroll
    for (int i = 0; i < 8; i++) ws[tid * 8 + i] = l[i] * inv;
    __syncthreads();

    if (ds == 0) {
        float* attn = out + B_ * D_;
#pragma unroll
        for (int i = 0; i < 8; i++) attn[b * T_ + tid * 8 + i] = ws[tid * 8 + i];
    }

    const int d = ds * 128 + tid;
    const float* fb = feat + (size_t)b * T_ * D_ + d;
    float acc = 0.f;
#pragma unroll 4
    for (int t = 0; t < T_; t++) acc += ws[t] * fb[(size_t)t * D_];
    out[b * D_ + d] = acc;
}

// ---------------------------------------------------------------------------
extern "C" void kernel_launch(void* const* d_in, const int* in_sizes, int n_in,
                              void* d_out, int out_size) {
    const float* feat   = (const float*)d_in[0];
    const float* hidden = (const float*)d_in[1];
    const float* W1w    = (const float*)d_in[2];
    const float* W1b    = (const float*)d_in[3];
    const float* W2w    = (const float*)d_in[4];
    const float* W2b    = (const float*)d_in[5];
    const float* Vw     = (const float*)d_in[6];
    const float* Vb     = (const float*)d_in[7];
    float* out = (float*)d_out;

    static bool attr_set = false;
    if (!attr_set) {
        cudaFuncSetAttribute(score_kernel, cudaFuncAttributeMaxDynamicSharedMemorySize,
                             SMEM_TOTAL);
        attr_set = true;
    }

    fsplit_kernel<<<BT * D_ / 4 / 256, 256>>>(feat);
    w1split_kernel<<<dim3(U_ / 32, D_ / 32), dim3(32, 8)>>>(W1w);
    projh_kernel<<<dim3(U_ / 128, B_ / 8), 128>>>(hidden, W2w, W2b);
    score_kernel<<<dim3(4, BT / 128), 512, SMEM_TOTAL>>>(W1b, Vw);
    softmax_ctx_kernel<<<dim3(B_, D_ / 128), 128>>>(feat, Vb, out);
}

// round 6
// speedup vs baseline: 1.1397x; 1.1397x over previous
#include <cuda_runtime.h>
#include <cuda_bf16.h>
#include <math.h>

#define B_ 64
#define T_ 1024
#define D_ 512
#define U_ 1024
#define BT (B_ * T_)

// ---------------- device scratch (no allocation allowed) ----------------
__device__ __align__(128) __nv_bfloat16 g_fhi[BT * D_];     // 64 MB
__device__ __align__(128) __nv_bfloat16 g_flo[BT * D_];     // 64 MB
__device__ __align__(128) __nv_bfloat16 g_w1t_hi[U_ * D_];  // [n][k], 1 MB
__device__ __align__(128) __nv_bfloat16 g_w1t_lo[U_ * D_];
__device__ float g_projh[B_ * U_];
__device__ float g_lpart[4][BT];   // per-n-quarter logit partials
__device__ float g_ws[BT];         // softmax weights

// ---------------- PTX helpers ----------------
__device__ __forceinline__ unsigned smem_u32(const void* p) {
    unsigned a;
    asm("{ .reg .u64 t; cvta.to.shared.u64 t, %1; cvt.u32.u64 %0, t; }"
        : "=r"(a) : "l"(p));
    return a;
}
__device__ __forceinline__ void cpa16(unsigned dst, const void* src) {
    asm volatile("cp.async.cg.shared.global [%0], [%1], 16;" :: "r"(dst), "l"(src));
}
__device__ __forceinline__ void cpa_commit() { asm volatile("cp.async.commit_group;"); }
__device__ __forceinline__ void ldsm4(unsigned addr, unsigned& r0, unsigned& r1,
                                      unsigned& r2, unsigned& r3) {
    asm volatile("ldmatrix.sync.aligned.m8n8.x4.shared.b16 {%0,%1,%2,%3}, [%4];"
                 : "=r"(r0), "=r"(r1), "=r"(r2), "=r"(r3) : "r"(addr));
}
__device__ __forceinline__ void mma16816(float* c, unsigned a0, unsigned a1,
                                         unsigned a2, unsigned a3,
                                         unsigned b0, unsigned b1) {
    asm volatile(
        "mma.sync.aligned.m16n8k16.row.col.f32.bf16.bf16.f32 "
        "{%0,%1,%2,%3}, {%4,%5,%6,%7}, {%8,%9}, {%0,%1,%2,%3};"
        : "+f"(c[0]), "+f"(c[1]), "+f"(c[2]), "+f"(c[3])
        : "r"(a0), "r"(a1), "r"(a2), "r"(a3), "r"(b0), "r"(b1));
}

// ---------------- smem layout for score kernel ----------------
#define STAGE 49152            // A (128x64 bf16 = 16KB) + B (256x64 bf16 = 32KB)
#define OFF_BT 16384           // B offset within stage
#define OFF_PH 196608          // 256 floats
#define OFF_V  197632          // 256 floats
#define OFF_RED 198656         // 128 x 8 floats
#define SMEM_TOTAL 202752

// ---------------------------------------------------------------------------
// split feat fp32 -> bf16 hi/lo
// ---------------------------------------------------------------------------
__global__ void fsplit_kernel(const float* __restrict__ feat) {
    long i = (long)blockIdx.x * 256 + threadIdx.x;   // one float4 per thread
    float4 v = ((const float4*)feat)[i];
    __nv_bfloat16 ha = __float2bfloat16(v.x), hb = __float2bfloat16(v.y);
    __nv_bfloat16 hc = __float2bfloat16(v.z), hd = __float2bfloat16(v.w);
    float la = v.x - __bfloat162float(ha), lb = v.y - __bfloat162float(hb);
    float lc = v.z - __bfloat162float(hc), ld = v.w - __bfloat162float(hd);
    uint2 hw, lw;
    hw.x = (unsigned)__bfloat16_as_ushort(ha) | ((unsigned)__bfloat16_as_ushort(hb) << 16);
    hw.y = (unsigned)__bfloat16_as_ushort(hc) | ((unsigned)__bfloat16_as_ushort(hd) << 16);
    lw.x = (unsigned)__bfloat16_as_ushort(__float2bfloat16(la)) |
           ((unsigned)__bfloat16_as_ushort(__float2bfloat16(lb)) << 16);
    lw.y = (unsigned)__bfloat16_as_ushort(__float2bfloat16(lc)) |
           ((unsigned)__bfloat16_as_ushort(__float2bfloat16(ld)) << 16);
    ((uint2*)g_fhi)[i] = hw;
    ((uint2*)g_flo)[i] = lw;
}

// ---------------------------------------------------------------------------
// transpose + split W1 [D,U] -> g_w1t_{hi,lo} [U][D]
// ---------------------------------------------------------------------------
__global__ void w1split_kernel(const float* __restrict__ W1) {
    __shared__ float tile[32][33];
    const int n0 = blockIdx.x * 32, k0 = blockIdx.y * 32;
    const int tx = threadIdx.x;
    for (int r = threadIdx.y; r < 32; r += 8)
        tile[r][tx] = W1[(size_t)(k0 + r) * U_ + n0 + tx];
    __syncthreads();
    for (int rr = threadIdx.y; rr < 32; rr += 8) {
        float v = tile[tx][rr];                   // W1[k0+tx][n0+rr]
        __nv_bfloat16 h = __float2bfloat16(v);
        size_t o = (size_t)(n0 + rr) * D_ + k0 + tx;
        g_w1t_hi[o] = h;
        g_w1t_lo[o] = __float2bfloat16(v - __bfloat162float(h));
    }
}

// ---------------------------------------------------------------------------
// proj_h[b,u] = hidden[b,:] @ W2[:,u] + W2_b[u];  grid (U/128, B/8), 128 thr
// ---------------------------------------------------------------------------
__global__ void projh_kernel(const float* __restrict__ hidden,
                             const float* __restrict__ W2,
                             const float* __restrict__ W2b) {
    __shared__ __align__(16) float hs[8][D_];
    const int tid = threadIdx.x;
    const int u = blockIdx.x * 128 + tid;
    const int b0 = blockIdx.y * 8;
#pragma unroll
    for (int i = 0; i < 8; i++)
        ((float4*)hs)[tid + i * 128] = ((const float4*)(hidden + (size_t)b0 * D_))[tid + i * 128];
    __syncthreads();
    float acc[8];
#pragma unroll
    for (int i = 0; i < 8; i++) acc[i] = 0.f;
#pragma unroll 4
    for (int k = 0; k < D_; k++) {
        float w = W2[(size_t)k * U_ + u];
#pragma unroll
        for (int bb = 0; bb < 8; bb++) acc[bb] += hs[bb][k] * w;
    }
    float bias = W2b[u];
#pragma unroll
    for (int bb = 0; bb < 8; bb++) g_projh[(size_t)(b0 + bb) * U_ + u] = acc[bb] + bias;
}

// ---------------------------------------------------------------------------
// score kernel: mma.sync bf16 (3-term split) GEMM + tanh + V-dot epilogue
// (unchanged from R5 — at HMMA ceiling)
// ---------------------------------------------------------------------------
__global__ void __launch_bounds__(512, 1)
score_kernel(const float* __restrict__ W1b, const float* __restrict__ Vw) {
    extern __shared__ __align__(1024) char smem[];
    const unsigned sbase = smem_u32(smem);
    const int tid = threadIdx.x;
    const int wid = tid >> 5, lid = tid & 31;
    const int wm = wid & 1, wn = wid >> 1;       // 2 x 8 warp grid, tile 64m x 32n
    const int nq = blockIdx.x;
    const int bt0 = blockIdx.y * 128;
    const int b = bt0 >> 10;
    const int n0 = nq * 256;
    float* shPh = (float*)(smem + OFF_PH);
    float* shV  = (float*)(smem + OFF_V);
    float (*red)[8] = (float(*)[8])(smem + OFF_RED);

    if (tid < 256) {
        shPh[tid] = g_projh[(size_t)b * U_ + n0 + tid] + W1b[n0 + tid];
        shV[tid]  = Vw[n0 + tid];
    }

    unsigned a_src0, a_dst0, b_src0, b_dst0;
    {
        int row = tid >> 3, c16 = tid & 7;
        a_src0 = (unsigned)((bt0 + row) * D_ + c16 * 8);
        a_dst0 = row * 128 + ((c16 ^ (row & 7)) * 16);
        b_src0 = (unsigned)((n0 + row) * D_ + c16 * 8);
        b_dst0 = OFF_BT + row * 128 + ((c16 ^ (row & 7)) * 16);
    }

    const int lrow = lid & 15;
    const int lch  = lid >> 4;
    unsigned abase0, bbase0;
    {
        int row = wm * 64 + lrow;
        abase0 = row * 128 + ((lch ^ (row & 7)) * 16);
        int rowb = wn * 32 + lrow;
        bbase0 = OFF_BT + rowb * 128 + ((lch ^ (rowb & 7)) * 16);
    }

    float Cr[4][4][4];
#pragma unroll
    for (int mt = 0; mt < 4; mt++)
#pragma unroll
        for (int nt = 0; nt < 4; nt++)
#pragma unroll
            for (int j = 0; j < 4; j++) Cr[mt][nt][j] = 0.f;

#pragma unroll
    for (int c = 0; c < 3; c++) {
        const int k0 = c * 64;
        const __nv_bfloat16* Asrc = g_fhi + k0;
        const __nv_bfloat16* Bsrc = g_w1t_hi + k0;
        const unsigned stg = sbase + c * STAGE;
#pragma unroll
        for (int i = 0; i < 2; i++)
            cpa16(stg + a_dst0 + i * 8192, Asrc + a_src0 + i * 32768);
#pragma unroll
        for (int i = 0; i < 4; i++)
            cpa16(stg + b_dst0 + i * 8192, Bsrc + b_src0 + i * 32768);
        cpa_commit();
    }

    for (int c = 0; c < 24; c++) {
        asm volatile("cp.async.wait_group 2;" ::: "memory");
        __syncthreads();
        if (c + 3 < 24) {
            const int cn = c + 3;
            const int seg = cn >> 3;
            const int k0 = (cn & 7) * 64;
            const __nv_bfloat16* Asrc = ((seg == 1) ? g_flo : g_fhi) + k0;
            const __nv_bfloat16* Bsrc = ((seg == 2) ? g_w1t_lo : g_w1t_hi) + k0;
            const unsigned stg = sbase + (cn & 3) * STAGE;
#pragma unroll
            for (int i = 0; i < 2; i++)
                cpa16(stg + a_dst0 + i * 8192, Asrc + a_src0 + i * 32768);
#pragma unroll
            for (int i = 0; i < 4; i++)
                cpa16(stg + b_dst0 + i * 8192, Bsrc + b_src0 + i * 32768);
        }
        cpa_commit();

        const unsigned Ab = sbase + (c & 3) * STAGE;
#pragma unroll
        for (int kk = 0; kk < 4; kk++) {
            const unsigned kx = kk << 5;
            unsigned a[4][4];
#pragma unroll
            for (int mt = 0; mt < 4; mt++)
                ldsm4(Ab + ((abase0 + mt * 2048) ^ kx),
                      a[mt][0], a[mt][1], a[mt][2], a[mt][3]);
            unsigned bf[4][2];
#pragma unroll
            for (int np = 0; np < 2; np++) {
                unsigned t0, t1, t2, t3;
                ldsm4(Ab + ((bbase0 + np * 2048) ^ kx), t0, t1, t2, t3);
                bf[np * 2][0] = t0; bf[np * 2][1] = t2;
                bf[np * 2 + 1][0] = t1; bf[np * 2 + 1][1] = t3;
            }
#pragma unroll
            for (int mt = 0; mt < 4; mt++)
#pragma unroll
                for (int nt = 0; nt < 4; nt++)
                    mma16816(Cr[mt][nt], a[mt][0], a[mt][1], a[mt][2], a[mt][3],
                             bf[nt][0], bf[nt][1]);
        }
    }

    float p0[4], p1[4];
#pragma unroll
    for (int mt = 0; mt < 4; mt++) { p0[mt] = 0.f; p1[mt] = 0.f; }
#pragma unroll
    for (int mt = 0; mt < 4; mt++)
#pragma unroll
        for (int nt = 0; nt < 4; nt++) {
            int nc = wn * 32 + nt * 8 + (lid & 3) * 2;
            float ph0 = shPh[nc], ph1 = shPh[nc + 1];
            float v0 = shV[nc], v1 = shV[nc + 1];
            p0[mt] += tanhf(Cr[mt][nt][0] + ph0) * v0
                    + tanhf(Cr[mt][nt][1] + ph1) * v1;
            p1[mt] += tanhf(Cr[mt][nt][2] + ph0) * v0
                    + tanhf(Cr[mt][nt][3] + ph1) * v1;
        }
#pragma unroll
    for (int mt = 0; mt < 4; mt++) {
        p0[mt] += __shfl_xor_sync(0xFFFFFFFFu, p0[mt], 1);
        p0[mt] += __shfl_xor_sync(0xFFFFFFFFu, p0[mt], 2);
        p1[mt] += __shfl_xor_sync(0xFFFFFFFFu, p1[mt], 1);
        p1[mt] += __shfl_xor_sync(0xFFFFFFFFu, p1[mt], 2);
    }
    if ((lid & 3) == 0) {
#pragma unroll
        for (int mt = 0; mt < 4; mt++) {
            int rl = wm * 64 + mt * 16 + (lid >> 2);
            red[rl][wn] = p0[mt];
            red[rl + 8][wn] = p1[mt];
        }
    }
    __syncthreads();
    if (tid < 128) {
        float s = red[tid][0] + red[tid][1] + red[tid][2] + red[tid][3]
                + red[tid][4] + red[tid][5] + red[tid][6] + red[tid][7];
        g_lpart[nq][bt0 + tid] = s;
    }
}

// ---------------------------------------------------------------------------
// softmax over T: grid B_, 256 threads; writes weights to g_ws + output
// ---------------------------------------------------------------------------
__global__ void softmax_w_kernel(const float* __restrict__ Vb,
                                 float* __restrict__ out) {
    __shared__ float rbuf[8];
    const int b = blockIdx.x;
    const int tid = threadIdx.x;
    const int wid = tid >> 5, lid = tid & 31;
    const float vb = Vb[0];

    float l[4];
    float mx = -1e30f;
#pragma unroll
    for (int i = 0; i < 4; i++) {
        int idx = b * T_ + tid * 4 + i;
        l[i] = g_lpart[0][idx] + g_lpart[1][idx] + g_lpart[2][idx] + g_lpart[3][idx] + vb;
        mx = fmaxf(mx, l[i]);
    }
#pragma unroll
    for (int s = 16; s > 0; s >>= 1) mx = fmaxf(mx, __shfl_xor_sync(~0u, mx, s));
    if (lid == 0) rbuf[wid] = mx;
    __syncthreads();
    float m8 = rbuf[lid & 7];
#pragma unroll
    for (int s = 4; s > 0; s >>= 1) m8 = fmaxf(m8, __shfl_xor_sync(~0u, m8, s));
    mx = __shfl_sync(~0u, m8, 0);

    float ssum = 0.f;
#pragma unroll
    for (int i = 0; i < 4; i++) {
        l[i] = expf(l[i] - mx);
        ssum += l[i];
    }
#pragma unroll
    for (int s = 16; s > 0; s >>= 1) ssum += __shfl_xor_sync(~0u, ssum, s);
    __syncthreads();
    if (lid == 0) rbuf[wid] = ssum;
    __syncthreads();
    float s8 = rbuf[lid & 7];
#pragma unroll
    for (int s = 4; s > 0; s >>= 1) s8 += __shfl_xor_sync(~0u, s8, s);
    const float inv = 1.0f / __shfl_sync(~0u, s8, 0);

    float4 w4 = make_float4(l[0] * inv, l[1] * inv, l[2] * inv, l[3] * inv);
    ((float4*)(g_ws + b * T_))[tid] = w4;
    ((float4*)(out + B_ * D_ + b * T_))[tid] = w4;
}

// ---------------------------------------------------------------------------
// context vector: grid (B_, D/128), 512 threads (4 T-quarters x 128 d-lanes)
// ---------------------------------------------------------------------------
__global__ void __launch_bounds__(512)
ctx_kernel(const float* __restrict__ feat, float* __restrict__ out) {
    __shared__ float ws[T_];
    __shared__ float red[4][128];
    const int b = blockIdx.x;
    const int d0 = blockIdx.y * 128;
    const int tid = threadIdx.x;
    const int dl = tid & 127;
    const int tq = tid >> 7;

    ((float2*)ws)[tid] = ((const float2*)(g_ws + b * T_))[tid];
    __syncthreads();

    const float* fb = feat + (size_t)b * T_ * D_ + (size_t)tq * 256 * D_ + d0 + dl;
    const float* wq = ws + tq * 256;
    float acc = 0.f;
#pragma unroll 8
    for (int t = 0; t < 256; t++) acc += wq[t] * fb[(size_t)t * D_];
    red[tq][dl] = acc;
    __syncthreads();
    if (tid < 128)
        out[b * D_ + d0 + tid] = red[0][tid] + red[1][tid] + red[2][tid] + red[3][tid];
}

// ---------------------------------------------------------------------------
extern "C" void kernel_launch(void* const* d_in, const int* in_sizes, int n_in,
                              void* d_out, int out_size) {
    const float* feat   = (const float*)d_in[0];
    const float* hidden = (const float*)d_in[1];
    const float* W1w    = (const float*)d_in[2];
    const float* W1b    = (const float*)d_in[3];
    const float* W2w    = (const float*)d_in[4];
    const float* W2b    = (const float*)d_in[5];
    const float* Vw     = (const float*)d_in[6];
    const float* Vb     = (const float*)d_in[7];
    float* out = (float*)d_out;

    static bool attr_set = false;
    if (!attr_set) {
        cudaFuncSetAttribute(score_kernel, cudaFuncAttributeMaxDynamicSharedMemorySize,
                             SMEM_TOTAL);
        attr_set = true;
    }

    fsplit_kernel<<<BT * D_ / 4 / 256, 256>>>(feat);
    w1split_kernel<<<dim3(U_ / 32, D_ / 32), dim3(32, 8)>>>(W1w);
    projh_kernel<<<dim3(U_ / 128, B_ / 8), 128>>>(hidden, W2w, W2b);
    score_kernel<<<dim3(4, BT / 128), 512, SMEM_TOTAL>>>(W1b, Vw);
    softmax_w_kernel<<<B_, 256>>>(Vb, out);
    ctx_kernel<<<dim3(B_, D_ / 128), 512>>>(feat, out);
}

// round 8
// speedup vs baseline: 1.2449x; 1.0923x over previous
#include <cuda_runtime.h>
#include <cuda_fp16.h>
#include <math.h>

#define B_ 64
#define T_ 1024
#define D_ 512
#define U_ 1024
#define BT (B_ * T_)

// ---------------- device scratch (no allocation allowed) ----------------
__device__ __align__(128) __half g_fhi[BT * D_];   // 64 MB
__device__ __align__(128) __half g_flo[BT * D_];   // 64 MB (fp16 residual)
__device__ __align__(128) __half g_w1t[U_ * D_];   // [n][k], 1 MB
__device__ float g_projh[B_ * U_];
__device__ float g_lpart[4][BT];   // per-n-quarter logit partials
__device__ float g_ws[BT];         // softmax weights

// ---------------- PTX helpers ----------------
__device__ __forceinline__ unsigned smem_u32(const void* p) {
    unsigned a;
    asm("{ .reg .u64 t; cvta.to.shared.u64 t, %1; cvt.u32.u64 %0, t; }"
        : "=r"(a) : "l"(p));
    return a;
}
__device__ __forceinline__ void cpa16(unsigned dst, const void* src) {
    asm volatile("cp.async.cg.shared.global [%0], [%1], 16;" :: "r"(dst), "l"(src));
}
__device__ __forceinline__ void cpa_commit() { asm volatile("cp.async.commit_group;"); }
__device__ __forceinline__ void ldsm4(unsigned addr, unsigned& r0, unsigned& r1,
                                      unsigned& r2, unsigned& r3) {
    asm volatile("ldmatrix.sync.aligned.m8n8.x4.shared.b16 {%0,%1,%2,%3}, [%4];"
                 : "=r"(r0), "=r"(r1), "=r"(r2), "=r"(r3) : "r"(addr));
}
__device__ __forceinline__ void mma16816(float* c, unsigned a0, unsigned a1,
                                         unsigned a2, unsigned a3,
                                         unsigned b0, unsigned b1) {
    asm volatile(
        "mma.sync.aligned.m16n8k16.row.col.f32.f16.f16.f32 "
        "{%0,%1,%2,%3}, {%4,%5,%6,%7}, {%8,%9}, {%0,%1,%2,%3};"
        : "+f"(c[0]), "+f"(c[1]), "+f"(c[2]), "+f"(c[3])
        : "r"(a0), "r"(a1), "r"(a2), "r"(a3), "r"(b0), "r"(b1));
}

// ---------------- smem layout for score kernel ----------------
#define STAGE 65536            // A_hi(16KB) + A_lo(16KB) + B(32KB)
#define OFF_ALO 16384
#define OFF_BT  32768
#define OFF_PH 196608          // 256 floats
#define OFF_V  197632          // 256 floats
#define OFF_RED 198656         // 128 x 8 floats
#define SMEM_TOTAL 202752

// ---------------------------------------------------------------------------
// split feat fp32 -> fp16 hi + fp16 residual
// ---------------------------------------------------------------------------
__global__ void fsplit_kernel(const float* __restrict__ feat) {
    long i = (long)blockIdx.x * 256 + threadIdx.x;   // one float4 per thread
    float4 v = ((const float4*)feat)[i];
    __half ha = __float2half_rn(v.x), hb = __float2half_rn(v.y);
    __half hc = __float2half_rn(v.z), hd = __float2half_rn(v.w);
    float la = v.x - __half2float(ha), lb = v.y - __half2float(hb);
    float lc = v.z - __half2float(hc), ld = v.w - __half2float(hd);
    uint2 hw, lw;
    hw.x = (unsigned)__half_as_ushort(ha) | ((unsigned)__half_as_ushort(hb) << 16);
    hw.y = (unsigned)__half_as_ushort(hc) | ((unsigned)__half_as_ushort(hd) << 16);
    lw.x = (unsigned)__half_as_ushort(__float2half_rn(la)) |
           ((unsigned)__half_as_ushort(__float2half_rn(lb)) << 16);
    lw.y = (unsigned)__half_as_ushort(__float2half_rn(lc)) |
           ((unsigned)__half_as_ushort(__float2half_rn(ld)) << 16);
    ((uint2*)g_fhi)[i] = hw;
    ((uint2*)g_flo)[i] = lw;
}

// ---------------------------------------------------------------------------
// transpose W1 [D,U] -> g_w1t [U][D] fp16
// ---------------------------------------------------------------------------
__global__ void w1split_kernel(const float* __restrict__ W1) {
    __shared__ float tile[32][33];
    const int n0 = blockIdx.x * 32, k0 = blockIdx.y * 32;
    const int tx = threadIdx.x;
    for (int r = threadIdx.y; r < 32; r += 8)
        tile[r][tx] = W1[(size_t)(k0 + r) * U_ + n0 + tx];
    __syncthreads();
    for (int rr = threadIdx.y; rr < 32; rr += 8)
        g_w1t[(size_t)(n0 + rr) * D_ + k0 + tx] = __float2half_rn(tile[tx][rr]);
}

// ---------------------------------------------------------------------------
// proj_h[b,u] = hidden[b,:] @ W2[:,u] + W2_b[u];  grid (U/128, B/8), 128 thr
// ---------------------------------------------------------------------------
__global__ void projh_kernel(const float* __restrict__ hidden,
                             const float* __restrict__ W2,
                             const float* __restrict__ W2b) {
    __shared__ __align__(16) float hs[8][D_];
    const int tid = threadIdx.x;
    const int u = blockIdx.x * 128 + tid;
    const int b0 = blockIdx.y * 8;
#pragma unroll
    for (int i = 0; i < 8; i++)
        ((float4*)hs)[tid + i * 128] = ((const float4*)(hidden + (size_t)b0 * D_))[tid + i * 128];
    __syncthreads();
    float acc[8];
#pragma unroll
    for (int i = 0; i < 8; i++) acc[i] = 0.f;
#pragma unroll 4
    for (int k = 0; k < D_; k++) {
        float w = W2[(size_t)k * U_ + u];
#pragma unroll
        for (int bb = 0; bb < 8; bb++) acc[bb] += hs[bb][k] * w;
    }
    float bias = W2b[u];
#pragma unroll
    for (int bb = 0; bb < 8; bb++) g_projh[(size_t)(b0 + bb) * U_ + u] = acc[bb] + bias;
}

// ---------------------------------------------------------------------------
// score kernel: mma.sync fp16 (2-term A split, shared B) + tanh + V-dot
// CTA tile 128(M) x 256(N), 8 real-K chunks of 64, both A segments per chunk
// 3-stage ring, prefetch distance 2 (stage (c+2)%3 == (c-1)%3, freed by barrier)
// grid (4 n-quarters, BT/128), 512 threads (16 warps, 64x32 warp tiles)
// ---------------------------------------------------------------------------
__global__ void __launch_bounds__(512, 1)
score_kernel(const float* __restrict__ W1b, const float* __restrict__ Vw) {
    extern __shared__ __align__(1024) char smem[];
    const unsigned sbase = smem_u32(smem);
    const int tid = threadIdx.x;
    const int wid = tid >> 5, lid = tid & 31;
    const int wm = wid & 1, wn = wid >> 1;       // 2 x 8 warp grid, tile 64m x 32n
    const int nq = blockIdx.x;
    const int bt0 = blockIdx.y * 128;
    const int b = bt0 >> 10;
    const int n0 = nq * 256;
    float* shPh = (float*)(smem + OFF_PH);
    float* shV  = (float*)(smem + OFF_V);
    float (*red)[8] = (float(*)[8])(smem + OFF_RED);

    if (tid < 256) {
        shPh[tid] = g_projh[(size_t)b * U_ + n0 + tid] + W1b[n0 + tid];
        shV[tid]  = Vw[n0 + tid];
    }

    // loop-invariant cp.async offsets
    unsigned a_src0, a_dst0, b_src0, b_dst0;
    {
        int row = tid >> 3, c16 = tid & 7;
        a_src0 = (unsigned)((bt0 + row) * D_ + c16 * 8);
        a_dst0 = row * 128 + ((c16 ^ (row & 7)) * 16);
        b_src0 = (unsigned)((n0 + row) * D_ + c16 * 8);
        b_dst0 = OFF_BT + row * 128 + ((c16 ^ (row & 7)) * 16);
    }

    // loop-invariant ldmatrix bases (k-step enters via XOR)
    const int lrow = lid & 15;
    const int lch  = lid >> 4;
    unsigned abase0, bbase0;
    {
        int row = wm * 64 + lrow;
        abase0 = row * 128 + ((lch ^ (row & 7)) * 16);
        int rowb = wn * 32 + lrow;
        bbase0 = OFF_BT + rowb * 128 + ((lch ^ (rowb & 7)) * 16);
    }

    float Cr[4][4][4];
#pragma unroll
    for (int mt = 0; mt < 4; mt++)
#pragma unroll
        for (int nt = 0; nt < 4; nt++)
#pragma unroll
            for (int j = 0; j < 4; j++) Cr[mt][nt][j] = 0.f;

    // prologue: chunks 0,1 into stages 0,1 (one commit group each)
#pragma unroll
    for (int c = 0; c < 2; c++) {
        const int k0 = c * 64;
        const unsigned stg = sbase + c * STAGE;
#pragma unroll
        for (int i = 0; i < 2; i++)
            cpa16(stg + a_dst0 + i * 8192, g_fhi + k0 + a_src0 + i * 32768);
#pragma unroll
        for (int i = 0; i < 2; i++)
            cpa16(stg + OFF_ALO + a_dst0 + i * 8192, g_flo + k0 + a_src0 + i * 32768);
#pragma unroll
        for (int i = 0; i < 4; i++)
            cpa16(stg + b_dst0 + i * 8192, g_w1t + k0 + b_src0 + i * 32768);
        cpa_commit();
    }

    for (int c = 0; c < 8; c++) {
        // chunk c ready when all but the newest 1 group are done
        asm volatile("cp.async.wait_group 1;" ::: "memory");
        __syncthreads();   // also frees stage (c-1)%3 == (c+2)%3 for rewrite
        if (c + 2 < 8) {
            const int k0 = (c + 2) * 64;
            const unsigned stg = sbase + ((c + 2) % 3) * STAGE;
#pragma unroll
            for (int i = 0; i < 2; i++)
                cpa16(stg + a_dst0 + i * 8192, g_fhi + k0 + a_src0 + i * 32768);
#pragma unroll
            for (int i = 0; i < 2; i++)
                cpa16(stg + OFF_ALO + a_dst0 + i * 8192, g_flo + k0 + a_src0 + i * 32768);
#pragma unroll
            for (int i = 0; i < 4; i++)
                cpa16(stg + b_dst0 + i * 8192, g_w1t + k0 + b_src0 + i * 32768);
        }
        cpa_commit();   // exactly one group per iteration keeps accounting exact

        const unsigned Ab = sbase + (c % 3) * STAGE;
#pragma unroll
        for (int kk = 0; kk < 4; kk++) {
            const unsigned kx = kk << 5;
            unsigned bf[4][2];
#pragma unroll
            for (int np = 0; np < 2; np++) {
                unsigned t0, t1, t2, t3;
                ldsm4(Ab + ((bbase0 + np * 2048) ^ kx), t0, t1, t2, t3);
                bf[np * 2][0] = t0; bf[np * 2][1] = t2;
                bf[np * 2 + 1][0] = t1; bf[np * 2 + 1][1] = t3;
            }
            unsigned ah[4][4];
#pragma unroll
            for (int mt = 0; mt < 4; mt++)
                ldsm4(Ab + ((abase0 + mt * 2048) ^ kx),
                      ah[mt][0], ah[mt][1], ah[mt][2], ah[mt][3]);
#pragma unroll
            for (int mt = 0; mt < 4; mt++)
#pragma unroll
                for (int nt = 0; nt < 4; nt++)
                    mma16816(Cr[mt][nt], ah[mt][0], ah[mt][1], ah[mt][2], ah[mt][3],
                             bf[nt][0], bf[nt][1]);
            unsigned al[4][4];
#pragma unroll
            for (int mt = 0; mt < 4; mt++)
                ldsm4(Ab + ((abase0 + OFF_ALO + mt * 2048) ^ kx),
                      al[mt][0], al[mt][1], al[mt][2], al[mt][3]);
#pragma unroll
            for (int mt = 0; mt < 4; mt++)
#pragma unroll
                for (int nt = 0; nt < 4; nt++)
                    mma16816(Cr[mt][nt], al[mt][0], al[mt][1], al[mt][2], al[mt][3],
                             bf[nt][0], bf[nt][1]);
        }
    }

    // ---- epilogue: tanh + V-dot on fragments ----
    float p0[4], p1[4];
#pragma unroll
    for (int mt = 0; mt < 4; mt++) { p0[mt] = 0.f; p1[mt] = 0.f; }
#pragma unroll
    for (int mt = 0; mt < 4; mt++)
#pragma unroll
        for (int nt = 0; nt < 4; nt++) {
            int nc = wn * 32 + nt * 8 + (lid & 3) * 2;
            float ph0 = shPh[nc], ph1 = shPh[nc + 1];
            float v0 = shV[nc], v1 = shV[nc + 1];
            p0[mt] += tanhf(Cr[mt][nt][0] + ph0) * v0
                    + tanhf(Cr[mt][nt][1] + ph1) * v1;
            p1[mt] += tanhf(Cr[mt][nt][2] + ph0) * v0
                    + tanhf(Cr[mt][nt][3] + ph1) * v1;
        }
#pragma unroll
    for (int mt = 0; mt < 4; mt++) {
        p0[mt] += __shfl_xor_sync(0xFFFFFFFFu, p0[mt], 1);
        p0[mt] += __shfl_xor_sync(0xFFFFFFFFu, p0[mt], 2);
        p1[mt] += __shfl_xor_sync(0xFFFFFFFFu, p1[mt], 1);
        p1[mt] += __shfl_xor_sync(0xFFFFFFFFu, p1[mt], 2);
    }
    if ((lid & 3) == 0) {
#pragma unroll
        for (int mt = 0; mt < 4; mt++) {
            int rl = wm * 64 + mt * 16 + (lid >> 2);
            red[rl][wn] = p0[mt];
            red[rl + 8][wn] = p1[mt];
        }
    }
    __syncthreads();
    if (tid < 128) {
        float s = red[tid][0] + red[tid][1] + red[tid][2] + red[tid][3]
                + red[tid][4] + red[tid][5] + red[tid][6] + red[tid][7];
        g_lpart[nq][bt0 + tid] = s;
    }
}

// ---------------------------------------------------------------------------
// softmax over T: grid B_, 256 threads; writes weights to g_ws + output
// ---------------------------------------------------------------------------
__global__ void softmax_w_kernel(const float* __restrict__ Vb,
                                 float* __restrict__ out) {
    __shared__ float rbuf[8];
    const int b = blockIdx.x;
    const int tid = threadIdx.x;
    const int wid = tid >> 5, lid = tid & 31;
    const float vb = Vb[0];

    float l[4];
    float mx = -1e30f;
#pragma unroll
    for (int i = 0; i < 4; i++) {
        int idx = b * T_ + tid * 4 + i;
        l[i] = g_lpart[0][idx] + g_lpart[1][idx] + g_lpart[2][idx] + g_lpart[3][idx] + vb;
        mx = fmaxf(mx, l[i]);
    }
#pragma unroll
    for (int s = 16; s > 0; s >>= 1) mx = fmaxf(mx, __shfl_xor_sync(~0u, mx, s));
    if (lid == 0) rbuf[wid] = mx;
    __syncthreads();
    float m8 = rbuf[lid & 7];
#pragma unroll
    for (int s = 4; s > 0; s >>= 1) m8 = fmaxf(m8, __shfl_xor_sync(~0u, m8, s));
    mx = __shfl_sync(~0u, m8, 0);

    float ssum = 0.f;
#pragma unroll
    for (int i = 0; i < 4; i++) {
        l[i] = expf(l[i] - mx);
        ssum += l[i];
    }
#pragma unroll
    for (int s = 16; s > 0; s >>= 1) ssum += __shfl_xor_sync(~0u, ssum, s);
    __syncthreads();
    if (lid == 0) rbuf[wid] = ssum;
    __syncthreads();
    float s8 = rbuf[lid & 7];
#pragma unroll
    for (int s = 4; s > 0; s >>= 1) s8 += __shfl_xor_sync(~0u, s8, s);
    const float inv = 1.0f / __shfl_sync(~0u, s8, 0);

    float4 w4 = make_float4(l[0] * inv, l[1] * inv, l[2] * inv, l[3] * inv);
    ((float4*)(g_ws + b * T_))[tid] = w4;
    ((float4*)(out + B_ * D_ + b * T_))[tid] = w4;
}

// ---------------------------------------------------------------------------
// context vector: grid (B_, D/128), 512 threads (4 T-quarters x 128 d-lanes)
// ---------------------------------------------------------------------------
__global__ void __launch_bounds__(512)
ctx_kernel(const float* __restrict__ feat, float* __restrict__ out) {
    __shared__ float ws[T_];
    __shared__ float red[4][128];
    const int b = blockIdx.x;
    const int d0 = blockIdx.y * 128;
    const int tid = threadIdx.x;
    const int dl = tid & 127;
    const int tq = tid >> 7;

    ((float2*)ws)[tid] = ((const float2*)(g_ws + b * T_))[tid];
    __syncthreads();

    const float* fb = feat + (size_t)b * T_ * D_ + (size_t)tq * 256 * D_ + d0 + dl;
    const float* wq = ws + tq * 256;
    float acc = 0.f;
#pragma unroll 8
    for (int t = 0; t < 256; t++) acc += wq[t] * fb[(size_t)t * D_];
    red[tq][dl] = acc;
    __syncthreads();
    if (tid < 128)
        out[b * D_ + d0 + tid] = red[0][tid] + red[1][tid] + red[2][tid] + red[3][tid];
}

// ---------------------------------------------------------------------------
extern "C" void kernel_launch(void* const* d_in, const int* in_sizes, int n_in,
                              void* d_out, int out_size) {
    const float* feat   = (const float*)d_in[0];
    const float* hidden = (const float*)d_in[1];
    const float* W1w    = (const float*)d_in[2];
    const float* W1b    = (const float*)d_in[3];
    const float* W2w    = (const float*)d_in[4];
    const float* W2b    = (const float*)d_in[5];
    const float* Vw     = (const float*)d_in[6];
    const float* Vb     = (const float*)d_in[7];
    float* out = (float*)d_out;

    static bool attr_set = false;
    if (!attr_set) {
        cudaFuncSetAttribute(score_kernel, cudaFuncAttributeMaxDynamicSharedMemorySize,
                             SMEM_TOTAL);
        attr_set = true;
    }

    fsplit_kernel<<<BT * D_ / 4 / 256, 256>>>(feat);
    w1split_kernel<<<dim3(U_ / 32, D_ / 32), dim3(32, 8)>>>(W1w);
    projh_kernel<<<dim3(U_ / 128, B_ / 8), 128>>>(hidden, W2w, W2b);
    score_kernel<<<dim3(4, BT / 128), 512, SMEM_TOTAL>>>(W1b, Vw);
    softmax_w_kernel<<<B_, 256>>>(Vb, out);
    ctx_kernel<<<dim3(B_, D_ / 128), 512>>>(feat, out);
}

// round 9
// speedup vs baseline: 2.3223x; 1.8655x over previous
#include <cuda_runtime.h>
#include <cuda_fp16.h>
#include <math.h>

#define B_ 64
#define T_ 1024
#define D_ 512
#define U_ 1024
#define BT (B_ * T_)

// ---------------- device scratch (no allocation allowed) ----------------
__device__ __align__(128) __half g_fhi[BT * D_];   // 64 MB
__device__ __align__(128) __half g_w1t[U_ * D_];   // [n][k], 1 MB
__device__ float g_projh[B_ * U_];
__device__ float g_lpart[4][BT];   // per-n-quarter logit partials
__device__ float g_ws[BT];         // softmax weights

// ---------------- PTX helpers ----------------
__device__ __forceinline__ unsigned smem_u32(const void* p) {
    unsigned a;
    asm("{ .reg .u64 t; cvta.to.shared.u64 t, %1; cvt.u32.u64 %0, t; }"
        : "=r"(a) : "l"(p));
    return a;
}
__device__ __forceinline__ void cpa16(unsigned dst, const void* src) {
    asm volatile("cp.async.cg.shared.global [%0], [%1], 16;" :: "r"(dst), "l"(src));
}
__device__ __forceinline__ void cpa_commit() { asm volatile("cp.async.commit_group;"); }
__device__ __forceinline__ void ldsm4(unsigned addr, unsigned& r0, unsigned& r1,
                                      unsigned& r2, unsigned& r3) {
    asm volatile("ldmatrix.sync.aligned.m8n8.x4.shared.b16 {%0,%1,%2,%3}, [%4];"
                 : "=r"(r0), "=r"(r1), "=r"(r2), "=r"(r3) : "r"(addr));
}
__device__ __forceinline__ void mma16816(float* c, unsigned a0, unsigned a1,
                                         unsigned a2, unsigned a3,
                                         unsigned b0, unsigned b1) {
    asm volatile(
        "mma.sync.aligned.m16n8k16.row.col.f32.f16.f16.f32 "
        "{%0,%1,%2,%3}, {%4,%5,%6,%7}, {%8,%9}, {%0,%1,%2,%3};"
        : "+f"(c[0]), "+f"(c[1]), "+f"(c[2]), "+f"(c[3])
        : "r"(a0), "r"(a1), "r"(a2), "r"(a3), "r"(b0), "r"(b1));
}

// ---------------- smem layout for score kernel ----------------
#define STAGE 49152            // A (128x64 fp16 = 16KB) + B (256x64 fp16 = 32KB)
#define OFF_BT 16384
#define OFF_PH 196608          // 256 floats
#define OFF_V  197632          // 256 floats
#define OFF_RED 198656         // 128 x 8 floats
#define SMEM_TOTAL 202752

// ---------------------------------------------------------------------------
// convert feat fp32 -> fp16
// ---------------------------------------------------------------------------
__global__ void fsplit_kernel(const float* __restrict__ feat) {
    long i = (long)blockIdx.x * 256 + threadIdx.x;   // one float4 per thread
    float4 v = ((const float4*)feat)[i];
    uint2 hw;
    hw.x = (unsigned)__half_as_ushort(__float2half_rn(v.x)) |
           ((unsigned)__half_as_ushort(__float2half_rn(v.y)) << 16);
    hw.y = (unsigned)__half_as_ushort(__float2half_rn(v.z)) |
           ((unsigned)__half_as_ushort(__float2half_rn(v.w)) << 16);
    ((uint2*)g_fhi)[i] = hw;
}

// ---------------------------------------------------------------------------
// transpose W1 [D,U] -> g_w1t [U][D] fp16
// ---------------------------------------------------------------------------
__global__ void w1split_kernel(const float* __restrict__ W1) {
    __shared__ float tile[32][33];
    const int n0 = blockIdx.x * 32, k0 = blockIdx.y * 32;
    const int tx = threadIdx.x;
    for (int r = threadIdx.y; r < 32; r += 8)
        tile[r][tx] = W1[(size_t)(k0 + r) * U_ + n0 + tx];
    __syncthreads();
    for (int rr = threadIdx.y; rr < 32; rr += 8)
        g_w1t[(size_t)(n0 + rr) * D_ + k0 + tx] = __float2half_rn(tile[tx][rr]);
}

// ---------------------------------------------------------------------------
// proj_h[b,u] = hidden[b,:] @ W2[:,u] + W2_b[u];  grid (U/128, B/8), 128 thr
// ---------------------------------------------------------------------------
__global__ void projh_kernel(const float* __restrict__ hidden,
                             const float* __restrict__ W2,
                             const float* __restrict__ W2b) {
    __shared__ __align__(16) float hs[8][D_];
    const int tid = threadIdx.x;
    const int u = blockIdx.x * 128 + tid;
    const int b0 = blockIdx.y * 8;
#pragma unroll
    for (int i = 0; i < 8; i++)
        ((float4*)hs)[tid + i * 128] = ((const float4*)(hidden + (size_t)b0 * D_))[tid + i * 128];
    __syncthreads();
    float acc[8];
#pragma unroll
    for (int i = 0; i < 8; i++) acc[i] = 0.f;
#pragma unroll 4
    for (int k = 0; k < D_; k++) {
        float w = W2[(size_t)k * U_ + u];
#pragma unroll
        for (int bb = 0; bb < 8; bb++) acc[bb] += hs[bb][k] * w;
    }
    float bias = W2b[u];
#pragma unroll
    for (int bb = 0; bb < 8; bb++) g_projh[(size_t)(b0 + bb) * U_ + u] = acc[bb] + bias;
}

// ---------------------------------------------------------------------------
// score kernel: mma.sync fp16 GEMM + tanh + V-dot epilogue
// CTA tile 128(M) x 256(N), 8 K chunks of 64
// 4-stage ring, prefetch distance 3 (R6-proven pattern)
// grid (4 n-quarters, BT/128), 512 threads (16 warps, 64x32 warp tiles)
// ---------------------------------------------------------------------------
__global__ void __launch_bounds__(512, 1)
score_kernel(const float* __restrict__ W1b, const float* __restrict__ Vw) {
    extern __shared__ __align__(1024) char smem[];
    const unsigned sbase = smem_u32(smem);
    const int tid = threadIdx.x;
    const int wid = tid >> 5, lid = tid & 31;
    const int wm = wid & 1, wn = wid >> 1;       // 2 x 8 warp grid, tile 64m x 32n
    const int nq = blockIdx.x;
    const int bt0 = blockIdx.y * 128;
    const int b = bt0 >> 10;
    const int n0 = nq * 256;
    float* shPh = (float*)(smem + OFF_PH);
    float* shV  = (float*)(smem + OFF_V);
    float (*red)[8] = (float(*)[8])(smem + OFF_RED);

    if (tid < 256) {
        shPh[tid] = g_projh[(size_t)b * U_ + n0 + tid] + W1b[n0 + tid];
        shV[tid]  = Vw[n0 + tid];
    }

    // loop-invariant cp.async offsets
    unsigned a_src0, a_dst0, b_src0, b_dst0;
    {
        int row = tid >> 3, c16 = tid & 7;
        a_src0 = (unsigned)((bt0 + row) * D_ + c16 * 8);
        a_dst0 = row * 128 + ((c16 ^ (row & 7)) * 16);
        b_src0 = (unsigned)((n0 + row) * D_ + c16 * 8);
        b_dst0 = OFF_BT + row * 128 + ((c16 ^ (row & 7)) * 16);
    }

    // loop-invariant ldmatrix bases (k-step enters via XOR)
    const int lrow = lid & 15;
    const int lch  = lid >> 4;
    unsigned abase0, bbase0;
    {
        int row = wm * 64 + lrow;
        abase0 = row * 128 + ((lch ^ (row & 7)) * 16);
        int rowb = wn * 32 + lrow;
        bbase0 = OFF_BT + rowb * 128 + ((lch ^ (rowb & 7)) * 16);
    }

    float Cr[4][4][4];
#pragma unroll
    for (int mt = 0; mt < 4; mt++)
#pragma unroll
        for (int nt = 0; nt < 4; nt++)
#pragma unroll
            for (int j = 0; j < 4; j++) Cr[mt][nt][j] = 0.f;

    // prologue: chunks 0..2 into stages 0..2
#pragma unroll
    for (int c = 0; c < 3; c++) {
        const int k0 = c * 64;
        const unsigned stg = sbase + c * STAGE;
#pragma unroll
        for (int i = 0; i < 2; i++)
            cpa16(stg + a_dst0 + i * 8192, g_fhi + k0 + a_src0 + i * 32768);
#pragma unroll
        for (int i = 0; i < 4; i++)
            cpa16(stg + b_dst0 + i * 8192, g_w1t + k0 + b_src0 + i * 32768);
        cpa_commit();
    }

    for (int c = 0; c < 8; c++) {
        asm volatile("cp.async.wait_group 2;" ::: "memory");
        __syncthreads();
        if (c + 3 < 8) {
            const int k0 = (c + 3) * 64;
            const unsigned stg = sbase + ((c + 3) & 3) * STAGE;
#pragma unroll
            for (int i = 0; i < 2; i++)
                cpa16(stg + a_dst0 + i * 8192, g_fhi + k0 + a_src0 + i * 32768);
#pragma unroll
            for (int i = 0; i < 4; i++)
                cpa16(stg + b_dst0 + i * 8192, g_w1t + k0 + b_src0 + i * 32768);
        }
        cpa_commit();

        const unsigned Ab = sbase + (c & 3) * STAGE;
#pragma unroll
        for (int kk = 0; kk < 4; kk++) {
            const unsigned kx = kk << 5;
            unsigned bf[4][2];
#pragma unroll
            for (int np = 0; np < 2; np++) {
                unsigned t0, t1, t2, t3;
                ldsm4(Ab + ((bbase0 + np * 2048) ^ kx), t0, t1, t2, t3);
                bf[np * 2][0] = t0; bf[np * 2][1] = t2;
                bf[np * 2 + 1][0] = t1; bf[np * 2 + 1][1] = t3;
            }
            unsigned ah[4][4];
#pragma unroll
            for (int mt = 0; mt < 4; mt++)
                ldsm4(Ab + ((abase0 + mt * 2048) ^ kx),
                      ah[mt][0], ah[mt][1], ah[mt][2], ah[mt][3]);
#pragma unroll
            for (int mt = 0; mt < 4; mt++)
#pragma unroll
                for (int nt = 0; nt < 4; nt++)
                    mma16816(Cr[mt][nt], ah[mt][0], ah[mt][1], ah[mt][2], ah[mt][3],
                             bf[nt][0], bf[nt][1]);
        }
    }

    // ---- epilogue: tanh + V-dot on fragments ----
    float p0[4], p1[4];
#pragma unroll
    for (int mt = 0; mt < 4; mt++) { p0[mt] = 0.f; p1[mt] = 0.f; }
#pragma unroll
    for (int mt = 0; mt < 4; mt++)
#pragma unroll
        for (int nt = 0; nt < 4; nt++) {
            int nc = wn * 32 + nt * 8 + (lid & 3) * 2;
            float ph0 = shPh[nc], ph1 = shPh[nc + 1];
            float v0 = shV[nc], v1 = shV[nc + 1];
            p0[mt] += tanhf(Cr[mt][nt][0] + ph0) * v0
                    + tanhf(Cr[mt][nt][1] + ph1) * v1;
            p1[mt] += tanhf(Cr[mt][nt][2] + ph0) * v0
                    + tanhf(Cr[mt][nt][3] + ph1) * v1;
        }
#pragma unroll
    for (int mt = 0; mt < 4; mt++) {
        p0[mt] += __shfl_xor_sync(0xFFFFFFFFu, p0[mt], 1);
        p0[mt] += __shfl_xor_sync(0xFFFFFFFFu, p0[mt], 2);
        p1[mt] += __shfl_xor_sync(0xFFFFFFFFu, p1[mt], 1);
        p1[mt] += __shfl_xor_sync(0xFFFFFFFFu, p1[mt], 2);
    }
    if ((lid & 3) == 0) {
#pragma unroll
        for (int mt = 0; mt < 4; mt++) {
            int rl = wm * 64 + mt * 16 + (lid >> 2);
            red[rl][wn] = p0[mt];
            red[rl + 8][wn] = p1[mt];
        }
    }
    __syncthreads();
    if (tid < 128) {
        float s = red[tid][0] + red[tid][1] + red[tid][2] + red[tid][3]
                + red[tid][4] + red[tid][5] + red[tid][6] + red[tid][7];
        g_lpart[nq][bt0 + tid] = s;
    }
}

// ---------------------------------------------------------------------------
// softmax over T: grid B_, 256 threads; writes weights to g_ws + output
// ---------------------------------------------------------------------------
__global__ void softmax_w_kernel(const float* __restrict__ Vb,
                                 float* __restrict__ out) {
    __shared__ float rbuf[8];
    const int b = blockIdx.x;
    const int tid = threadIdx.x;
    const int wid = tid >> 5, lid = tid & 31;
    const float vb = Vb[0];

    float l[4];
    float mx = -1e30f;
#pragma unroll
    for (int i = 0; i < 4; i++) {
        int idx = b * T_ + tid * 4 + i;
        l[i] = g_lpart[0][idx] + g_lpart[1][idx] + g_lpart[2][idx] + g_lpart[3][idx] + vb;
        mx = fmaxf(mx, l[i]);
    }
#pragma unroll
    for (int s = 16; s > 0; s >>= 1) mx = fmaxf(mx, __shfl_xor_sync(~0u, mx, s));
    if (lid == 0) rbuf[wid] = mx;
    __syncthreads();
    float m8 = rbuf[lid & 7];
#pragma unroll
    for (int s = 4; s > 0; s >>= 1) m8 = fmaxf(m8, __shfl_xor_sync(~0u, m8, s));
    mx = __shfl_sync(~0u, m8, 0);

    float ssum = 0.f;
#pragma unroll
    for (int i = 0; i < 4; i++) {
        l[i] = expf(l[i] - mx);
        ssum += l[i];
    }
#pragma unroll
    for (int s = 16; s > 0; s >>= 1) ssum += __shfl_xor_sync(~0u, ssum, s);
    __syncthreads();
    if (lid == 0) rbuf[wid] = ssum;
    __syncthreads();
    float s8 = rbuf[lid & 7];
#pragma unroll
    for (int s = 4; s > 0; s >>= 1) s8 += __shfl_xor_sync(~0u, s8, s);
    const float inv = 1.0f / __shfl_sync(~0u, s8, 0);

    float4 w4 = make_float4(l[0] * inv, l[1] * inv, l[2] * inv, l[3] * inv);
    ((float4*)(g_ws + b * T_))[tid] = w4;
    ((float4*)(out + B_ * D_ + b * T_))[tid] = w4;
}

// ---------------------------------------------------------------------------
// context vector: grid (B_, D/128), 512 threads (4 T-quarters x 128 d-lanes)
// reads fp16 features (error contribution ~1e-5, negligible)
// ---------------------------------------------------------------------------
__global__ void __launch_bounds__(512)
ctx_kernel(float* __restrict__ out) {
    __shared__ float ws[T_];
    __shared__ float red[4][128];
    const int b = blockIdx.x;
    const int d0 = blockIdx.y * 128;
    const int tid = threadIdx.x;
    const int dl = tid & 127;
    const int tq = tid >> 7;

    ((float2*)ws)[tid] = ((const float2*)(g_ws + b * T_))[tid];
    __syncthreads();

    const __half* fb = g_fhi + (size_t)b * T_ * D_ + (size_t)tq * 256 * D_ + d0 + dl;
    const float* wq = ws + tq * 256;
    float acc = 0.f;
#pragma unroll 8
    for (int t = 0; t < 256; t++) acc += wq[t] * __half2float(fb[(size_t)t * D_]);
    red[tq][dl] = acc;
    __syncthreads();
    if (tid < 128)
        out[b * D_ + d0 + tid] = red[0][tid] + red[1][tid] + red[2][tid] + red[3][tid];
}

// ---------------------------------------------------------------------------
extern "C" void kernel_launch(void* const* d_in, const int* in_sizes, int n_in,
                              void* d_out, int out_size) {
    const float* feat   = (const float*)d_in[0];
    const float* hidden = (const float*)d_in[1];
    const float* W1w    = (const float*)d_in[2];
    const float* W1b    = (const float*)d_in[3];
    const float* W2w    = (const float*)d_in[4];
    const float* W2b    = (const float*)d_in[5];
    const float* Vw     = (const float*)d_in[6];
    const float* Vb     = (const float*)d_in[7];
    float* out = (float*)d_out;

    static bool attr_set = false;
    if (!attr_set) {
        cudaFuncSetAttribute(score_kernel, cudaFuncAttributeMaxDynamicSharedMemorySize,
                             SMEM_TOTAL);
        attr_set = true;
    }

    fsplit_kernel<<<BT * D_ / 4 / 256, 256>>>(feat);
    w1split_kernel<<<dim3(U_ / 32, D_ / 32), dim3(32, 8)>>>(W1w);
    projh_kernel<<<dim3(U_ / 128, B_ / 8), 128>>>(hidden, W2w, W2b);
    score_kernel<<<dim3(4, BT / 128), 512, SMEM_TOTAL>>>(W1b, Vw);
    softmax_w_kernel<<<B_, 256>>>(Vb, out);
    ctx_kernel<<<dim3(B_, D_ / 128), 512>>>(out);
}

// round 10
// speedup vs baseline: 2.3387x; 1.0070x over previous
#include <cuda_runtime.h>
#include <cuda_fp16.h>
#include <math.h>

#define B_ 64
#define T_ 1024
#define D_ 512
#define U_ 1024
#define BT (B_ * T_)

// ---------------- device scratch (no allocation allowed) ----------------
__device__ __align__(128) __half g_fhi[BT * D_];   // 64 MB
__device__ __align__(128) __half g_w1t[U_ * D_];   // [n][k], 1 MB
__device__ float g_projh[B_ * U_];
__device__ float g_lpart[4][BT];   // per-n-quarter logit partials
__device__ float g_ws[BT];         // softmax weights

// ---------------- PTX helpers ----------------
__device__ __forceinline__ unsigned smem_u32(const void* p) {
    unsigned a;
    asm("{ .reg .u64 t; cvta.to.shared.u64 t, %1; cvt.u32.u64 %0, t; }"
        : "=r"(a) : "l"(p));
    return a;
}
__device__ __forceinline__ void cpa16(unsigned dst, const void* src) {
    asm volatile("cp.async.cg.shared.global [%0], [%1], 16;" :: "r"(dst), "l"(src));
}
__device__ __forceinline__ void cpa_commit() { asm volatile("cp.async.commit_group;"); }
__device__ __forceinline__ void ldsm4(unsigned addr, unsigned& r0, unsigned& r1,
                                      unsigned& r2, unsigned& r3) {
    asm volatile("ldmatrix.sync.aligned.m8n8.x4.shared.b16 {%0,%1,%2,%3}, [%4];"
                 : "=r"(r0), "=r"(r1), "=r"(r2), "=r"(r3) : "r"(addr));
}
__device__ __forceinline__ void mma16816(float* c, unsigned a0, unsigned a1,
                                         unsigned a2, unsigned a3,
                                         unsigned b0, unsigned b1) {
    asm volatile(
        "mma.sync.aligned.m16n8k16.row.col.f32.f16.f16.f32 "
        "{%0,%1,%2,%3}, {%4,%5,%6,%7}, {%8,%9}, {%0,%1,%2,%3};"
        : "+f"(c[0]), "+f"(c[1]), "+f"(c[2]), "+f"(c[3])
        : "r"(a0), "r"(a1), "r"(a2), "r"(a3), "r"(b0), "r"(b1));
}
// fast tanh: 1 - 2/(e^{2x}+1). abs err ~2e-7 (EX2/RCP ulp-level), handles +/-inf.
__device__ __forceinline__ float ftanh(float x) {
    float e = __expf(2.0f * x);
    return 1.0f - __fdividef(2.0f, e + 1.0f);
}

// ---------------- smem layout for score kernel ----------------
#define STAGE 49152            // A (128x64 fp16 = 16KB) + B (256x64 fp16 = 32KB)
#define OFF_BT 16384
#define OFF_PH 196608          // 256 floats
#define OFF_V  197632          // 256 floats
#define OFF_RED 198656         // 128 x 8 floats
#define SMEM_TOTAL 202752

// ---------------------------------------------------------------------------
// prep kernel: fused  fsplit (fp32->fp16 feat) + W1 transpose + proj_h GEMV
// grid = NF_BLK + NW_BLK + NP_BLK blocks of 256 threads
// ---------------------------------------------------------------------------
#define NF_BLK (BT * D_ / 4 / 256)   // 32768
#define NW_BLK 512                   // (U/32) x (D/32)
#define NP_BLK 32                    // (U/256) x (B/8)
__global__ void __launch_bounds__(256)
prep_kernel(const float* __restrict__ feat, const float* __restrict__ W1,
            const float* __restrict__ hidden, const float* __restrict__ W2,
            const float* __restrict__ W2b) {
    __shared__ __align__(16) char sbuf[16384];
    const int bid = blockIdx.x;
    const int tid = threadIdx.x;

    if (bid < NF_BLK) {
        // ---- feat fp32 -> fp16 ----
        long i = (long)bid * 256 + tid;
        float4 v = ((const float4*)feat)[i];
        uint2 hw;
        hw.x = (unsigned)__half_as_ushort(__float2half_rn(v.x)) |
               ((unsigned)__half_as_ushort(__float2half_rn(v.y)) << 16);
        hw.y = (unsigned)__half_as_ushort(__float2half_rn(v.z)) |
               ((unsigned)__half_as_ushort(__float2half_rn(v.w)) << 16);
        ((uint2*)g_fhi)[i] = hw;
    } else if (bid < NF_BLK + NW_BLK) {
        // ---- W1 [D,U] -> g_w1t [U][D] fp16 ----
        float (*tile)[33] = (float(*)[33])sbuf;
        const int wb = bid - NF_BLK;
        const int n0 = (wb & 31) * 32, k0 = (wb >> 5) * 32;
        const int tx = tid & 31, ty = tid >> 5;
        for (int r = ty; r < 32; r += 8)
            tile[r][tx] = W1[(size_t)(k0 + r) * U_ + n0 + tx];
        __syncthreads();
        for (int rr = ty; rr < 32; rr += 8)
            g_w1t[(size_t)(n0 + rr) * D_ + k0 + tx] = __float2half_rn(tile[tx][rr]);
    } else {
        // ---- proj_h[b,u] = hidden[b,:] @ W2[:,u] + W2_b[u] ----
        float (*hs)[D_] = (float(*)[D_])sbuf;
        const int pb = bid - NF_BLK - NW_BLK;
        const int u = (pb & 3) * 256 + tid;
        const int b0 = (pb >> 2) * 8;
#pragma unroll
        for (int i = 0; i < 4; i++)
            ((float4*)hs)[tid + i * 256] =
                ((const float4*)(hidden + (size_t)b0 * D_))[tid + i * 256];
        __syncthreads();
        float acc[8];
#pragma unroll
        for (int i = 0; i < 8; i++) acc[i] = 0.f;
#pragma unroll 4
        for (int k = 0; k < D_; k++) {
            float w = W2[(size_t)k * U_ + u];
#pragma unroll
            for (int bb = 0; bb < 8; bb++) acc[bb] += hs[bb][k] * w;
        }
        float bias = W2b[u];
#pragma unroll
        for (int bb = 0; bb < 8; bb++)
            g_projh[(size_t)(b0 + bb) * U_ + u] = acc[bb] + bias;
    }
}

// ---------------------------------------------------------------------------
// score kernel: mma.sync fp16 GEMM + fast-tanh + V-dot epilogue
// CTA tile 128(M) x 256(N), 8 K chunks of 64, 4-stage ring (distance 3)
// grid (4 n-quarters, BT/128), 512 threads (16 warps, 64x32 warp tiles)
// ---------------------------------------------------------------------------
__global__ void __launch_bounds__(512, 1)
score_kernel(const float* __restrict__ W1b, const float* __restrict__ Vw) {
    extern __shared__ __align__(1024) char smem[];
    const unsigned sbase = smem_u32(smem);
    const int tid = threadIdx.x;
    const int wid = tid >> 5, lid = tid & 31;
    const int wm = wid & 1, wn = wid >> 1;       // 2 x 8 warp grid, tile 64m x 32n
    const int nq = blockIdx.x;
    const int bt0 = blockIdx.y * 128;
    const int b = bt0 >> 10;
    const int n0 = nq * 256;
    float* shPh = (float*)(smem + OFF_PH);
    float* shV  = (float*)(smem + OFF_V);
    float (*red)[8] = (float(*)[8])(smem + OFF_RED);

    if (tid < 256) {
        shPh[tid] = g_projh[(size_t)b * U_ + n0 + tid] + W1b[n0 + tid];
        shV[tid]  = Vw[n0 + tid];
    }

    // loop-invariant cp.async offsets
    unsigned a_src0, a_dst0, b_src0, b_dst0;
    {
        int row = tid >> 3, c16 = tid & 7;
        a_src0 = (unsigned)((bt0 + row) * D_ + c16 * 8);
        a_dst0 = row * 128 + ((c16 ^ (row & 7)) * 16);
        b_src0 = (unsigned)((n0 + row) * D_ + c16 * 8);
        b_dst0 = OFF_BT + row * 128 + ((c16 ^ (row & 7)) * 16);
    }

    // loop-invariant ldmatrix bases (k-step enters via XOR)
    const int lrow = lid & 15;
    const int lch  = lid >> 4;
    unsigned abase0, bbase0;
    {
        int row = wm * 64 + lrow;
        abase0 = row * 128 + ((lch ^ (row & 7)) * 16);
        int rowb = wn * 32 + lrow;
        bbase0 = OFF_BT + rowb * 128 + ((lch ^ (rowb & 7)) * 16);
    }

    float Cr[4][4][4];
#pragma unroll
    for (int mt = 0; mt < 4; mt++)
#pragma unroll
        for (int nt = 0; nt < 4; nt++)
#pragma unroll
            for (int j = 0; j < 4; j++) Cr[mt][nt][j] = 0.f;

    // prologue: chunks 0..2 into stages 0..2
#pragma unroll
    for (int c = 0; c < 3; c++) {
        const int k0 = c * 64;
        const unsigned stg = sbase + c * STAGE;
#pragma unroll
        for (int i = 0; i < 2; i++)
            cpa16(stg + a_dst0 + i * 8192, g_fhi + k0 + a_src0 + i * 32768);
#pragma unroll
        for (int i = 0; i < 4; i++)
            cpa16(stg + b_dst0 + i * 8192, g_w1t + k0 + b_src0 + i * 32768);
        cpa_commit();
    }

    for (int c = 0; c < 8; c++) {
        asm volatile("cp.async.wait_group 2;" ::: "memory");
        __syncthreads();
        if (c + 3 < 8) {
            const int k0 = (c + 3) * 64;
            const unsigned stg = sbase + ((c + 3) & 3) * STAGE;
#pragma unroll
            for (int i = 0; i < 2; i++)
                cpa16(stg + a_dst0 + i * 8192, g_fhi + k0 + a_src0 + i * 32768);
#pragma unroll
            for (int i = 0; i < 4; i++)
                cpa16(stg + b_dst0 + i * 8192, g_w1t + k0 + b_src0 + i * 32768);
        }
        cpa_commit();

        const unsigned Ab = sbase + (c & 3) * STAGE;
#pragma unroll
        for (int kk = 0; kk < 4; kk++) {
            const unsigned kx = kk << 5;
            unsigned bf[4][2];
#pragma unroll
            for (int np = 0; np < 2; np++) {
                unsigned t0, t1, t2, t3;
                ldsm4(Ab + ((bbase0 + np * 2048) ^ kx), t0, t1, t2, t3);
                bf[np * 2][0] = t0; bf[np * 2][1] = t2;
                bf[np * 2 + 1][0] = t1; bf[np * 2 + 1][1] = t3;
            }
            unsigned ah[4][4];
#pragma unroll
            for (int mt = 0; mt < 4; mt++)
                ldsm4(Ab + ((abase0 + mt * 2048) ^ kx),
                      ah[mt][0], ah[mt][1], ah[mt][2], ah[mt][3]);
#pragma unroll
            for (int mt = 0; mt < 4; mt++)
#pragma unroll
                for (int nt = 0; nt < 4; nt++)
                    mma16816(Cr[mt][nt], ah[mt][0], ah[mt][1], ah[mt][2], ah[mt][3],
                             bf[nt][0], bf[nt][1]);
        }
    }

    // ---- epilogue: fast tanh + V-dot on fragments ----
    float p0[4], p1[4];
#pragma unroll
    for (int mt = 0; mt < 4; mt++) { p0[mt] = 0.f; p1[mt] = 0.f; }
#pragma unroll
    for (int mt = 0; mt < 4; mt++)
#pragma unroll
        for (int nt = 0; nt < 4; nt++) {
            int nc = wn * 32 + nt * 8 + (lid & 3) * 2;
            float ph0 = shPh[nc], ph1 = shPh[nc + 1];
            float v0 = shV[nc], v1 = shV[nc + 1];
            p0[mt] += ftanh(Cr[mt][nt][0] + ph0) * v0
                    + ftanh(Cr[mt][nt][1] + ph1) * v1;
            p1[mt] += ftanh(Cr[mt][nt][2] + ph0) * v0
                    + ftanh(Cr[mt][nt][3] + ph1) * v1;
        }
#pragma unroll
    for (int mt = 0; mt < 4; mt++) {
        p0[mt] += __shfl_xor_sync(0xFFFFFFFFu, p0[mt], 1);
        p0[mt] += __shfl_xor_sync(0xFFFFFFFFu, p0[mt], 2);
        p1[mt] += __shfl_xor_sync(0xFFFFFFFFu, p1[mt], 1);
        p1[mt] += __shfl_xor_sync(0xFFFFFFFFu, p1[mt], 2);
    }
    if ((lid & 3) == 0) {
#pragma unroll
        for (int mt = 0; mt < 4; mt++) {
            int rl = wm * 64 + mt * 16 + (lid >> 2);
            red[rl][wn] = p0[mt];
            red[rl + 8][wn] = p1[mt];
        }
    }
    __syncthreads();
    if (tid < 128) {
        float s = red[tid][0] + red[tid][1] + red[tid][2] + red[tid][3]
                + red[tid][4] + red[tid][5] + red[tid][6] + red[tid][7];
        g_lpart[nq][bt0 + tid] = s;
    }
}

// ---------------------------------------------------------------------------
// softmax over T: grid B_, 256 threads; writes weights to g_ws + output
// ---------------------------------------------------------------------------
__global__ void softmax_w_kernel(const float* __restrict__ Vb,
                                 float* __restrict__ out) {
    __shared__ float rbuf[8];
    const int b = blockIdx.x;
    const int tid = threadIdx.x;
    const int wid = tid >> 5, lid = tid & 31;
    const float vb = Vb[0];

    float l[4];
    float mx = -1e30f;
#pragma unroll
    for (int i = 0; i < 4; i++) {
        int idx = b * T_ + tid * 4 + i;
        l[i] = g_lpart[0][idx] + g_lpart[1][idx] + g_lpart[2][idx] + g_lpart[3][idx] + vb;
        mx = fmaxf(mx, l[i]);
    }
#pragma unroll
    for (int s = 16; s > 0; s >>= 1) mx = fmaxf(mx, __shfl_xor_sync(~0u, mx, s));
    if (lid == 0) rbuf[wid] = mx;
    __syncthreads();
    float m8 = rbuf[lid & 7];
#pragma unroll
    for (int s = 4; s > 0; s >>= 1) m8 = fmaxf(m8, __shfl_xor_sync(~0u, m8, s));
    mx = __shfl_sync(~0u, m8, 0);

    float ssum = 0.f;
#pragma unroll
    for (int i = 0; i < 4; i++) {
        l[i] = expf(l[i] - mx);
        ssum += l[i];
    }
#pragma unroll
    for (int s = 16; s > 0; s >>= 1) ssum += __shfl_xor_sync(~0u, ssum, s);
    __syncthreads();
    if (lid == 0) rbuf[wid] = ssum;
    __syncthreads();
    float s8 = rbuf[lid & 7];
#pragma unroll
    for (int s = 4; s > 0; s >>= 1) s8 += __shfl_xor_sync(~0u, s8, s);
    const float inv = 1.0f / __shfl_sync(~0u, s8, 0);

    float4 w4 = make_float4(l[0] * inv, l[1] * inv, l[2] * inv, l[3] * inv);
    ((float4*)(g_ws + b * T_))[tid] = w4;
    ((float4*)(out + B_ * D_ + b * T_))[tid] = w4;
}

// ---------------------------------------------------------------------------
// context vector: grid (B_, D/128), 512 threads (4 T-quarters x 128 d-lanes)
// ---------------------------------------------------------------------------
__global__ void __launch_bounds__(512)
ctx_kernel(float* __restrict__ out) {
    __shared__ float ws[T_];
    __shared__ float red[4][128];
    const int b = blockIdx.x;
    const int d0 = blockIdx.y * 128;
    const int tid = threadIdx.x;
    const int dl = tid & 127;
    const int tq = tid >> 7;

    ((float2*)ws)[tid] = ((const float2*)(g_ws + b * T_))[tid];
    __syncthreads();

    const __half* fb = g_fhi + (size_t)b * T_ * D_ + (size_t)tq * 256 * D_ + d0 + dl;
    const float* wq = ws + tq * 256;
    float acc = 0.f;
#pragma unroll 8
    for (int t = 0; t < 256; t++) acc += wq[t] * __half2float(fb[(size_t)t * D_]);
    red[tq][dl] = acc;
    __syncthreads();
    if (tid < 128)
        out[b * D_ + d0 + tid] = red[0][tid] + red[1][tid] + red[2][tid] + red[3][tid];
}

// ---------------------------------------------------------------------------
extern "C" void kernel_launch(void* const* d_in, const int* in_sizes, int n_in,
                              void* d_out, int out_size) {
    const float* feat   = (const float*)d_in[0];
    const float* hidden = (const float*)d_in[1];
    const float* W1w    = (const float*)d_in[2];
    const float* W1b    = (const float*)d_in[3];
    const float* W2w    = (const float*)d_in[4];
    const float* W2b    = (const float*)d_in[5];
    const float* Vw     = (const float*)d_in[6];
    const float* Vb     = (const float*)d_in[7];
    float* out = (float*)d_out;

    static bool attr_set = false;
    if (!attr_set) {
        cudaFuncSetAttribute(score_kernel, cudaFuncAttributeMaxDynamicSharedMemorySize,
                             SMEM_TOTAL);
        attr_set = true;
    }

    prep_kernel<<<NF_BLK + NW_BLK + NP_BLK, 256>>>(feat, W1w, hidden, W2w, W2b);
    score_kernel<<<dim3(4, BT / 128), 512, SMEM_TOTAL>>>(W1b, Vw);
    softmax_w_kernel<<<B_, 256>>>(Vb, out);
    ctx_kernel<<<dim3(B_, D_ / 128), 512>>>(out);
}